// round 13
// baseline (speedup 1.0000x reference)
#include <cuda_runtime.h>
#include <math.h>

#define KNN 20
#define THREADS 256
#define TILE_H 4096          // half-db per block (SoA: 3 * 16KB = 48KB)
#define CAP 56               // per-thread candidate buffer entries
#define STEP 32              // candidates per drain-check
#define IDXMASK 0x1FFFu      // 13 bits: global db idx < 8192
#define KEYMASK 0xFFFFE000u
#define MAXP 8192

__device__ float g_partials[1024];
// top-20 key lists: [sb*2+half][k][q]  (sb = side*B+b, 4 combos; q stride 1 -> coalesced)
__device__ unsigned g_knn[4 * 2 * KNN * MAXP];

__device__ __forceinline__ void bubble20(unsigned (&kd)[KNN], unsigned v) {
#pragma unroll
    for (int s = 0; s < KNN; ++s) {
        unsigned lo = min(kd[s], v);
        v = max(kd[s], v);
        kd[s] = lo;
    }
}

// ---------------- pass 1: half-db scan, emit per-query top-20 keys ----------------
__global__ void __launch_bounds__(THREADS, 2) knn_scan(
    const float* __restrict__ xyz1, const float* __restrict__ xyz2,
    const float* __restrict__ R12,  const float* __restrict__ t12,
    const float* __restrict__ R21,  const float* __restrict__ t21,
    const int* __restrict__ npts1,  const int* __restrict__ npts2,
    int B, int P)
{
    extern __shared__ float smemf[];
    float*    xs  = smemf;                     // [TILE_H] negated transformed x
    float*    ys  = smemf + TILE_H;
    float*    zs  = smemf + 2 * TILE_H;
    unsigned* buf = (unsigned*)(smemf + 3 * TILE_H);   // THREADS*CAP u32 = 56KB

    const int side  = blockIdx.z >> 1;
    const int half  = blockIdx.z & 1;
    const int b     = blockIdx.y;
    const int chunk = blockIdx.x;
    const int tid   = threadIdx.x;

    const float *q_xyz, *d_xyzp, *R, *T;
    int nq, ndb;
    const size_t o3 = (size_t)b * P * 3;
    if (side == 0) {
        q_xyz = xyz1 + o3; d_xyzp = xyz2 + o3;
        R = R12 + b * 9; T = t12 + b * 3;
        nq = npts1[b]; ndb = npts2[b];
    } else {
        q_xyz = xyz2 + o3; d_xyzp = xyz1 + o3;
        R = R21 + b * 9; T = t21 + b * 3;
        nq = npts2[b]; ndb = npts1[b];
    }

    const float r00 = R[0], r01 = R[1], r02 = R[2];
    const float r10 = R[3], r11 = R[4], r12_ = R[5];
    const float r20 = R[6], r21_ = R[7], r22 = R[8];
    const float t0 = T[0], t1 = T[1], t2 = T[2];

    const int dbBase = half * TILE_H;
    int cnt = ndb - dbBase;
    if (cnt < 0) cnt = 0;
    if (cnt > TILE_H) cnt = TILE_H;
    const int cntp = (cnt + STEP - 1) & ~(STEP - 1);

    const int q = chunk * THREADS + tid;
    const bool active = (q < nq) && (cnt > 0);

    // ---- stage half-tile: transform while loading, store NEGATED, SoA ----
    for (int j = tid; j < cntp; j += THREADS) {
        float sx, sy, sz;
        if (j < cnt) {
            const int gj = dbBase + j;
            const float x = d_xyzp[3 * gj];
            const float y = d_xyzp[3 * gj + 1];
            const float z = d_xyzp[3 * gj + 2];
            sx = -fmaf(r00, x, fmaf(r01, y, fmaf(r02, z, t0)));
            sy = -fmaf(r10, x, fmaf(r11, y, fmaf(r12_, z, t1)));
            sz = -fmaf(r20, x, fmaf(r21_, y, fmaf(r22, z, t2)));
        } else {
            sx = sy = sz = -1.0e15f;           // sentinel: enormous distance
        }
        xs[j] = sx; ys[j] = sy; zs[j] = sz;
    }
    __syncthreads();

    float qx = 0.f, qy = 0.f, qz = 0.f;
    if (q < nq) {
        qx = q_xyz[3 * q]; qy = q_xyz[3 * q + 1]; qz = q_xyz[3 * q + 2];
    }

    unsigned kd[KNN];
#pragma unroll
    for (int s = 0; s < KNN; ++s) kd[s] = 0xFFFFFFFFu;

    unsigned thr = active ? 0xFFFFFFFFu : 0u;
    unsigned* const mybase = buf + tid;        // stride THREADS: conflict-free
    unsigned*       wp     = mybase;
    unsigned* const wlimit = mybase + (CAP - STEP) * THREADS;

    for (int j0 = 0; j0 < cntp; j0 += STEP) {
        if (__any_sync(0xFFFFFFFFu, wp >= wlimit)) {
            for (unsigned* rp = mybase; rp < wp; rp += THREADS) {
                const unsigned v = *rp;
                if (v < kd[KNN - 1]) bubble20(kd, v);
            }
            wp = mybase;
            thr = active ? kd[KNN - 1] : 0u;
        }
        unsigned keys[STEP];
#pragma unroll
        for (int u = 0; u < STEP; ++u) {
            const float dx = qx + xs[j0 + u];
            const float dy = qy + ys[j0 + u];
            const float dz = qz + zs[j0 + u];
            const float d2 = fmaf(dx, dx, fmaf(dy, dy, dz * dz));
            keys[u] = (__float_as_uint(d2) & KEYMASK) | (unsigned)(dbBase + j0 + u);
        }
#pragma unroll
        for (int u = 0; u < STEP; ++u) {
            *wp = keys[u];
            wp += (keys[u] < thr) ? THREADS : 0;
        }
    }
    for (unsigned* rp = mybase; rp < wp; rp += THREADS) {
        const unsigned v = *rp;
        if (v < kd[KNN - 1]) bubble20(kd, v);
    }

    // ---- write sorted key list (coalesced: q is the fastest dim) ----
    if (q < P) {
        const int sb = side * B + b;
        unsigned* dst = g_knn + ((size_t)(sb * 2 + half) * KNN) * P + q;
#pragma unroll
        for (int k = 0; k < KNN; ++k) dst[(size_t)k * P] = kd[k];
    }
}

// ---------------- pass 2: merge halves + epilogue + block partials ----------------
__global__ void __launch_bounds__(THREADS) knn_merge(
    const float* __restrict__ xyz1, const float* __restrict__ xyz2,
    const float* __restrict__ hsv1, const float* __restrict__ hsv2,
    const float* __restrict__ nrm1, const float* __restrict__ nrm2,
    const float* __restrict__ res1, const float* __restrict__ res2,
    const float* __restrict__ R12,  const float* __restrict__ t12,
    const float* __restrict__ R21,  const float* __restrict__ t21,
    const int* __restrict__ npts1,  const int* __restrict__ npts2,
    int B, int P)
{
    const int side  = blockIdx.z;
    const int b     = blockIdx.y;
    const int chunk = blockIdx.x;
    const int tid   = threadIdx.x;

    const float *q_xyz, *q_hsv, *q_nrm, *q_res;
    const float *d_xyzp, *d_hsv, *d_nrm, *d_res;
    const float *R, *T;
    int nq;
    const size_t o3 = (size_t)b * P * 3;
    const size_t o1 = (size_t)b * P;
    if (side == 0) {
        q_xyz = xyz1 + o3; q_hsv = hsv1 + o3; q_nrm = nrm1 + o3; q_res = res1 + o1;
        d_xyzp = xyz2 + o3; d_hsv = hsv2 + o3; d_nrm = nrm2 + o3; d_res = res2 + o1;
        R = R12 + b * 9; T = t12 + b * 3;
        nq = npts1[b];
    } else {
        q_xyz = xyz2 + o3; q_hsv = hsv2 + o3; q_nrm = nrm2 + o3; q_res = res2 + o1;
        d_xyzp = xyz1 + o3; d_hsv = hsv1 + o3; d_nrm = nrm1 + o3; d_res = res1 + o1;
        R = R21 + b * 9; T = t21 + b * 3;
        nq = npts2[b];
    }

    const float r00 = R[0], r01 = R[1], r02 = R[2];
    const float r10 = R[3], r11 = R[4], r12_ = R[5];
    const float r20 = R[6], r21_ = R[7], r22 = R[8];
    const float t0 = T[0], t1 = T[1], t2 = T[2];

    const int q = chunk * THREADS + tid;
    const bool active = (q < nq);

    float acc = 0.0f;
    if (active) {
        const int sb = side * B + b;
        unsigned kd[KNN];
#pragma unroll
        for (int s = 0; s < KNN; ++s) kd[s] = 0xFFFFFFFFu;
        const unsigned* src = g_knn + ((size_t)(sb * 2) * KNN) * P + q;
#pragma unroll
        for (int k = 0; k < 2 * KNN; ++k) {
            const unsigned v = src[(size_t)k * P];
            if (v < kd[KNN - 1]) bubble20(kd, v);
        }

        const float qx = q_xyz[3 * q], qy = q_xyz[3 * q + 1], qz = q_xyz[3 * q + 2];
        const float ell = fmaxf(0.15f * (qz - 10.0f) * 0.1f, 0.15f);
        const float inv_ls = 1.0f / (ell * ell);
        const float hq0 = q_hsv[3 * q], hq1 = q_hsv[3 * q + 1], hq2 = q_hsv[3 * q + 2];
        const float n0 = q_nrm[3 * q], n1 = q_nrm[3 * q + 1], n2 = q_nrm[3 * q + 2];
        const float rq = q_res[q];
        // R^T * n_q so dot with RAW db normal equals n_q . (R n_db)
        const float tn0 = r00 * n0 + r10 * n1 + r20 * n2;
        const float tn1 = r01 * n0 + r11 * n1 + r21_ * n2;
        const float tn2 = r02 * n0 + r12_ * n1 + r22 * n2;
#pragma unroll
        for (int k = 0; k < KNN; ++k) {
            const int j = (int)(kd[k] & IDXMASK);
            const float x = d_xyzp[3 * j];
            const float y = d_xyzp[3 * j + 1];
            const float z = d_xyzp[3 * j + 2];
            // same fmaf tree as scan; qx - px == qx + (-px) bit-exact
            const float px = fmaf(r00, x, fmaf(r01, y, fmaf(r02, z, t0)));
            const float py = fmaf(r10, x, fmaf(r11, y, fmaf(r12_, z, t1)));
            const float pz = fmaf(r20, x, fmaf(r21_, y, fmaf(r22, z, t2)));
            const float dx = qx - px, dy = qy - py, dz = qz - pz;
            const float d2 = fmaf(dx, dx, fmaf(dy, dy, dz * dz));   // exact
            const float wd = expf(-d2 * inv_ls);
            const float h0 = d_hsv[3 * j]     - hq0;
            const float h1 = d_hsv[3 * j + 1] - hq1;
            const float h2 = d_hsv[3 * j + 2] - hq2;
            const float cd = sqrtf(fmaf(h0, h0, fmaf(h1, h1, h2 * h2)) + 1e-12f);
            const float wc = expf(-cd * 5.0f);
            const float rk = d_res[j];
            const float alpha = 0.2f / (0.1f + rq + rk);
            const float dn = tn0 * d_nrm[3 * j] + tn1 * d_nrm[3 * j + 1] + tn2 * d_nrm[3 * j + 2];
            const float wn = fmaxf(dn * alpha, 0.0f);
            acc += wd * wc * wn;
        }
    }

    __shared__ float red[THREADS];
    red[tid] = acc;
    __syncthreads();
#pragma unroll
    for (int s = THREADS / 2; s > 0; s >>= 1) {
        if (tid < s) red[tid] += red[tid + s];
        __syncthreads();
    }
    if (tid == 0) {
        const int bid = (side * gridDim.y + b) * gridDim.x + chunk;
        g_partials[bid] = red[0];
    }
}

__global__ void finalize_kernel(const int* __restrict__ npts1,
                                const int* __restrict__ npts2,
                                float* __restrict__ out,
                                int B, int nblk_side, int out_size)
{
    __shared__ double sh0[256], sh1[256];
    const int tid = threadIdx.x;
    double a0 = 0.0, a1 = 0.0;
    for (int i = tid; i < nblk_side; i += 256) {
        a0 += (double)g_partials[i];
        a1 += (double)g_partials[nblk_side + i];
    }
    sh0[tid] = a0; sh1[tid] = a1;
    __syncthreads();
#pragma unroll
    for (int s = 128; s > 0; s >>= 1) {
        if (tid < s) { sh0[tid] += sh0[tid + s]; sh1[tid] += sh1[tid + s]; }
        __syncthreads();
    }
    if (tid == 0) {
        double c1 = 0.0, c2 = 0.0;
        for (int i = 0; i < B; ++i) { c1 += npts1[i]; c2 += npts2[i]; }
        const double k1 = sh0[0] / (c1 * (double)KNN);
        const double k2 = sh1[0] / (c2 * (double)KNN);
        out[0] = (float)(0.5 * (k1 + k2));
        for (int i = 1; i < out_size; ++i) out[i] = 0.0f;
    }
}

extern "C" void kernel_launch(void* const* d_in, const int* in_sizes, int n_in,
                              void* d_out, int out_size)
{
    const float* xyz1 = (const float*)d_in[0];
    const float* xyz2 = (const float*)d_in[1];
    const float* hsv1 = (const float*)d_in[2];
    const float* hsv2 = (const float*)d_in[3];
    const float* nrm1 = (const float*)d_in[4];
    const float* nrm2 = (const float*)d_in[5];
    const float* res1 = (const float*)d_in[6];
    const float* res2 = (const float*)d_in[7];
    const float* R12  = (const float*)d_in[8];
    const float* t12  = (const float*)d_in[9];
    const float* R21  = (const float*)d_in[10];
    const float* t21  = (const float*)d_in[11];
    const int* npts1  = (const int*)d_in[12];
    const int* npts2  = (const int*)d_in[13];

    const int B = in_sizes[12];
    const int P = in_sizes[0] / (3 * B);
    const int chunks = (P + THREADS - 1) / THREADS;
    const size_t smem_scan = (size_t)3 * TILE_H * sizeof(float)
                           + (size_t)THREADS * CAP * sizeof(unsigned);   // 48KB + 56KB

    cudaFuncSetAttribute(knn_scan, cudaFuncAttributeMaxDynamicSharedMemorySize, (int)smem_scan);

    dim3 sgrid(chunks, B, 4);    // z = side*2 + half
    knn_scan<<<sgrid, THREADS, smem_scan>>>(xyz1, xyz2, R12, t12, R21, t21,
                                            npts1, npts2, B, P);
    dim3 mgrid(chunks, B, 2);
    knn_merge<<<mgrid, THREADS>>>(xyz1, xyz2, hsv1, hsv2, nrm1, nrm2,
                                  res1, res2, R12, t12, R21, t21,
                                  npts1, npts2, B, P);
    finalize_kernel<<<1, 256>>>(npts1, npts2, (float*)d_out, B, B * chunks, out_size);
}

// round 15
// speedup vs baseline: 1.1036x; 1.1036x over previous
#include <cuda_runtime.h>
#include <math.h>

#define KNN 20
#define THREADS 256
#define TILE_H 4096          // half-db per block (SoA: 3 * 16KB = 48KB)
#define CAP 56               // per-thread candidate buffer entries
#define STEP 32              // candidates per drain-check
#define IDXMASK 0x1FFFu      // 13 bits: global db idx < 8192
#define KEYMASK 0xFFFFE000u
#define MAXP 8192

__device__ float g_partials[1024];
// top-20 key lists: [sb*2+half][k][q]  (sb = side*B+b; q stride 1 -> coalesced)
__device__ unsigned g_knn[4 * 2 * KNN * MAXP];

__device__ __forceinline__ unsigned long long addx2(unsigned long long a, unsigned long long b) {
    unsigned long long r;
    asm("add.rn.f32x2 %0, %1, %2;" : "=l"(r) : "l"(a), "l"(b));
    return r;
}
__device__ __forceinline__ unsigned long long mulx2(unsigned long long a, unsigned long long b) {
    unsigned long long r;
    asm("mul.rn.f32x2 %0, %1, %2;" : "=l"(r) : "l"(a), "l"(b));
    return r;
}
__device__ __forceinline__ unsigned long long fmax2(unsigned long long a, unsigned long long b, unsigned long long c) {
    unsigned long long r;
    asm("fma.rn.f32x2 %0, %1, %2, %3;" : "=l"(r) : "l"(a), "l"(b), "l"(c));
    return r;
}
__device__ __forceinline__ unsigned long long bcast2(float x) {
    unsigned long long r;
    asm("mov.b64 %0, {%1, %1};" : "=l"(r) : "r"(__float_as_uint(x)));
    return r;
}

__device__ __forceinline__ void bubble20(unsigned (&kd)[KNN], unsigned v) {
#pragma unroll
    for (int s = 0; s < KNN; ++s) {
        unsigned lo = min(kd[s], v);
        v = max(kd[s], v);
        kd[s] = lo;
    }
}

// ---------------- pass 1: half-db scan, emit per-query top-20 keys ----------------
__global__ void __launch_bounds__(THREADS, 2) knn_scan(
    const float* __restrict__ xyz1, const float* __restrict__ xyz2,
    const float* __restrict__ R12,  const float* __restrict__ t12,
    const float* __restrict__ R21,  const float* __restrict__ t21,
    const int* __restrict__ npts1,  const int* __restrict__ npts2,
    int B, int P)
{
    extern __shared__ float smemf[];
    float*    xs  = smemf;                     // [TILE_H] negated transformed x
    float*    ys  = smemf + TILE_H;
    float*    zs  = smemf + 2 * TILE_H;
    unsigned* buf = (unsigned*)(smemf + 3 * TILE_H);   // THREADS*CAP u32 = 56KB

    const int side  = blockIdx.z >> 1;
    const int half  = blockIdx.z & 1;
    const int b     = blockIdx.y;
    const int chunk = blockIdx.x;
    const int tid   = threadIdx.x;

    const float *q_xyz, *d_xyzp, *R, *T;
    int nq, ndb;
    const size_t o3 = (size_t)b * P * 3;
    if (side == 0) {
        q_xyz = xyz1 + o3; d_xyzp = xyz2 + o3;
        R = R12 + b * 9; T = t12 + b * 3;
        nq = npts1[b]; ndb = npts2[b];
    } else {
        q_xyz = xyz2 + o3; d_xyzp = xyz1 + o3;
        R = R21 + b * 9; T = t21 + b * 3;
        nq = npts2[b]; ndb = npts1[b];
    }

    const float r00 = R[0], r01 = R[1], r02 = R[2];
    const float r10 = R[3], r11 = R[4], r12_ = R[5];
    const float r20 = R[6], r21_ = R[7], r22 = R[8];
    const float t0 = T[0], t1 = T[1], t2 = T[2];

    const int dbBase = half * TILE_H;
    int cnt = ndb - dbBase;
    if (cnt < 0) cnt = 0;
    if (cnt > TILE_H) cnt = TILE_H;
    const int cntp = (cnt + STEP - 1) & ~(STEP - 1);

    const int q = chunk * THREADS + tid;
    const bool active = (q < nq) && (cnt > 0);

    // ---- stage half-tile: transform while loading, store NEGATED, SoA ----
    for (int j = tid; j < cntp; j += THREADS) {
        float sx, sy, sz;
        if (j < cnt) {
            const int gj = dbBase + j;
            const float x = d_xyzp[3 * gj];
            const float y = d_xyzp[3 * gj + 1];
            const float z = d_xyzp[3 * gj + 2];
            sx = -fmaf(r00, x, fmaf(r01, y, fmaf(r02, z, t0)));
            sy = -fmaf(r10, x, fmaf(r11, y, fmaf(r12_, z, t1)));
            sz = -fmaf(r20, x, fmaf(r21_, y, fmaf(r22, z, t2)));
        } else {
            sx = sy = sz = -1.0e15f;           // sentinel: enormous distance
        }
        xs[j] = sx; ys[j] = sy; zs[j] = sz;
    }
    __syncthreads();

    float qx = 0.f, qy = 0.f, qz = 0.f;
    if (q < nq) {
        qx = q_xyz[3 * q]; qy = q_xyz[3 * q + 1]; qz = q_xyz[3 * q + 2];
    }
    const unsigned long long qx2 = bcast2(qx);
    const unsigned long long qy2 = bcast2(qy);
    const unsigned long long qz2 = bcast2(qz);

    unsigned kd[KNN];
#pragma unroll
    for (int s = 0; s < KNN; ++s) kd[s] = 0xFFFFFFFFu;

    unsigned thr = active ? 0xFFFFFFFFu : 0u;
    unsigned* const mybase = buf + tid;        // stride THREADS: conflict-free
    unsigned*       wp     = mybase;
    unsigned* const wlimit = mybase + (CAP - STEP) * THREADS;

    // ---- scan: packed-f32x2 phase A (LDS.128 batched), branchless phase B ----
    for (int j0 = 0; j0 < cntp; j0 += STEP) {
        if (__any_sync(0xFFFFFFFFu, wp >= wlimit)) {
            for (unsigned* rp = mybase; rp < wp; rp += THREADS) {
                const unsigned v = *rp;
                if (v < kd[KNN - 1]) bubble20(kd, v);
            }
            wp = mybase;
            thr = active ? kd[KNN - 1] : 0u;
        }
        unsigned keys[STEP];
#pragma unroll
        for (int g = 0; g < STEP / 4; ++g) {
            const int j4 = j0 + g * 4;
            const unsigned gidx = (unsigned)(dbBase + j4);
            // LDS.128: register pairs are ready-made f32x2 operands
            const ulonglong2 xv = *reinterpret_cast<const ulonglong2*>(xs + j4);
            const ulonglong2 yv = *reinterpret_cast<const ulonglong2*>(ys + j4);
            const ulonglong2 zv = *reinterpret_cast<const ulonglong2*>(zs + j4);
            {
                const unsigned long long dx = addx2(qx2, xv.x);
                const unsigned long long dy = addx2(qy2, yv.x);
                const unsigned long long dz = addx2(qz2, zv.x);
                const unsigned long long d2 = fmax2(dx, dx, fmax2(dy, dy, mulx2(dz, dz)));
                keys[g * 4 + 0] = ((unsigned)d2 & KEYMASK) | (gidx + 0u);
                keys[g * 4 + 1] = ((unsigned)(d2 >> 32) & KEYMASK) | (gidx + 1u);
            }
            {
                const unsigned long long dx = addx2(qx2, xv.y);
                const unsigned long long dy = addx2(qy2, yv.y);
                const unsigned long long dz = addx2(qz2, zv.y);
                const unsigned long long d2 = fmax2(dx, dx, fmax2(dy, dy, mulx2(dz, dz)));
                keys[g * 4 + 2] = ((unsigned)d2 & KEYMASK) | (gidx + 2u);
                keys[g * 4 + 3] = ((unsigned)(d2 >> 32) & KEYMASK) | (gidx + 3u);
            }
        }
        // Phase B: branchless pushes (always store, conditionally advance)
#pragma unroll
        for (int u = 0; u < STEP; ++u) {
            *wp = keys[u];
            wp += (keys[u] < thr) ? THREADS : 0;
        }
    }
    // final drain
    for (unsigned* rp = mybase; rp < wp; rp += THREADS) {
        const unsigned v = *rp;
        if (v < kd[KNN - 1]) bubble20(kd, v);
    }

    // ---- write sorted key list (coalesced: q is the fastest dim) ----
    if (q < P) {
        const int sb = side * B + b;
        unsigned* dst = g_knn + ((size_t)(sb * 2 + half) * KNN) * P + q;
#pragma unroll
        for (int k = 0; k < KNN; ++k) dst[(size_t)k * P] = kd[k];
    }
}

// ---------------- pass 2: merge halves + epilogue + block partials ----------------
__global__ void __launch_bounds__(THREADS) knn_merge(
    const float* __restrict__ xyz1, const float* __restrict__ xyz2,
    const float* __restrict__ hsv1, const float* __restrict__ hsv2,
    const float* __restrict__ nrm1, const float* __restrict__ nrm2,
    const float* __restrict__ res1, const float* __restrict__ res2,
    const float* __restrict__ R12,  const float* __restrict__ t12,
    const float* __restrict__ R21,  const float* __restrict__ t21,
    const int* __restrict__ npts1,  const int* __restrict__ npts2,
    int B, int P)
{
    const int side  = blockIdx.z;
    const int b     = blockIdx.y;
    const int chunk = blockIdx.x;
    const int tid   = threadIdx.x;

    const float *q_xyz, *q_hsv, *q_nrm, *q_res;
    const float *d_xyzp, *d_hsv, *d_nrm, *d_res;
    const float *R, *T;
    int nq;
    const size_t o3 = (size_t)b * P * 3;
    const size_t o1 = (size_t)b * P;
    if (side == 0) {
        q_xyz = xyz1 + o3; q_hsv = hsv1 + o3; q_nrm = nrm1 + o3; q_res = res1 + o1;
        d_xyzp = xyz2 + o3; d_hsv = hsv2 + o3; d_nrm = nrm2 + o3; d_res = res2 + o1;
        R = R12 + b * 9; T = t12 + b * 3;
        nq = npts1[b];
    } else {
        q_xyz = xyz2 + o3; q_hsv = hsv2 + o3; q_nrm = nrm2 + o3; q_res = res2 + o1;
        d_xyzp = xyz1 + o3; d_hsv = hsv1 + o3; d_nrm = nrm1 + o3; d_res = res1 + o1;
        R = R21 + b * 9; T = t21 + b * 3;
        nq = npts2[b];
    }

    const float r00 = R[0], r01 = R[1], r02 = R[2];
    const float r10 = R[3], r11 = R[4], r12_ = R[5];
    const float r20 = R[6], r21_ = R[7], r22 = R[8];
    const float t0 = T[0], t1 = T[1], t2 = T[2];

    const int q = chunk * THREADS + tid;
    const bool active = (q < nq);

    float acc = 0.0f;
    if (active) {
        const int sb = side * B + b;
        unsigned kd[KNN];
#pragma unroll
        for (int s = 0; s < KNN; ++s) kd[s] = 0xFFFFFFFFu;
        const unsigned* src = g_knn + ((size_t)(sb * 2) * KNN) * P + q;
#pragma unroll
        for (int k = 0; k < 2 * KNN; ++k) {
            const unsigned v = src[(size_t)k * P];
            if (v < kd[KNN - 1]) bubble20(kd, v);
        }

        const float qx = q_xyz[3 * q], qy = q_xyz[3 * q + 1], qz = q_xyz[3 * q + 2];
        const float ell = fmaxf(0.15f * (qz - 10.0f) * 0.1f, 0.15f);
        const float inv_ls = 1.0f / (ell * ell);
        const float hq0 = q_hsv[3 * q], hq1 = q_hsv[3 * q + 1], hq2 = q_hsv[3 * q + 2];
        const float n0 = q_nrm[3 * q], n1 = q_nrm[3 * q + 1], n2 = q_nrm[3 * q + 2];
        const float rq = q_res[q];
        // R^T * n_q so dot with RAW db normal equals n_q . (R n_db)
        const float tn0 = r00 * n0 + r10 * n1 + r20 * n2;
        const float tn1 = r01 * n0 + r11 * n1 + r21_ * n2;
        const float tn2 = r02 * n0 + r12_ * n1 + r22 * n2;
#pragma unroll
        for (int k = 0; k < KNN; ++k) {
            const int j = (int)(kd[k] & IDXMASK);
            const float x = d_xyzp[3 * j];
            const float y = d_xyzp[3 * j + 1];
            const float z = d_xyzp[3 * j + 2];
            // same fmaf tree as scan; qx - px == qx + (-px) bit-exact
            const float px = fmaf(r00, x, fmaf(r01, y, fmaf(r02, z, t0)));
            const float py = fmaf(r10, x, fmaf(r11, y, fmaf(r12_, z, t1)));
            const float pz = fmaf(r20, x, fmaf(r21_, y, fmaf(r22, z, t2)));
            const float dx = qx - px, dy = qy - py, dz = qz - pz;
            const float d2 = fmaf(dx, dx, fmaf(dy, dy, dz * dz));   // exact
            const float wd = expf(-d2 * inv_ls);
            const float h0 = d_hsv[3 * j]     - hq0;
            const float h1 = d_hsv[3 * j + 1] - hq1;
            const float h2 = d_hsv[3 * j + 2] - hq2;
            const float cd = sqrtf(fmaf(h0, h0, fmaf(h1, h1, h2 * h2)) + 1e-12f);
            const float wc = expf(-cd * 5.0f);
            const float rk = d_res[j];
            const float alpha = 0.2f / (0.1f + rq + rk);
            const float dn = tn0 * d_nrm[3 * j] + tn1 * d_nrm[3 * j + 1] + tn2 * d_nrm[3 * j + 2];
            const float wn = fmaxf(dn * alpha, 0.0f);
            acc += wd * wc * wn;
        }
    }

    __shared__ float red[THREADS];
    red[tid] = acc;
    __syncthreads();
#pragma unroll
    for (int s = THREADS / 2; s > 0; s >>= 1) {
        if (tid < s) red[tid] += red[tid + s];
        __syncthreads();
    }
    if (tid == 0) {
        const int bid = (side * gridDim.y + b) * gridDim.x + chunk;
        g_partials[bid] = red[0];
    }
}

__global__ void finalize_kernel(const int* __restrict__ npts1,
                                const int* __restrict__ npts2,
                                float* __restrict__ out,
                                int B, int nblk_side, int out_size)
{
    __shared__ double sh0[256], sh1[256];
    const int tid = threadIdx.x;
    double a0 = 0.0, a1 = 0.0;
    for (int i = tid; i < nblk_side; i += 256) {
        a0 += (double)g_partials[i];
        a1 += (double)g_partials[nblk_side + i];
    }
    sh0[tid] = a0; sh1[tid] = a1;
    __syncthreads();
#pragma unroll
    for (int s = 128; s > 0; s >>= 1) {
        if (tid < s) { sh0[tid] += sh0[tid + s]; sh1[tid] += sh1[tid + s]; }
        __syncthreads();
    }
    if (tid == 0) {
        double c1 = 0.0, c2 = 0.0;
        for (int i = 0; i < B; ++i) { c1 += npts1[i]; c2 += npts2[i]; }
        const double k1 = sh0[0] / (c1 * (double)KNN);
        const double k2 = sh1[0] / (c2 * (double)KNN);
        out[0] = (float)(0.5 * (k1 + k2));
        for (int i = 1; i < out_size; ++i) out[i] = 0.0f;
    }
}

extern "C" void kernel_launch(void* const* d_in, const int* in_sizes, int n_in,
                              void* d_out, int out_size)
{
    const float* xyz1 = (const float*)d_in[0];
    const float* xyz2 = (const float*)d_in[1];
    const float* hsv1 = (const float*)d_in[2];
    const float* hsv2 = (const float*)d_in[3];
    const float* nrm1 = (const float*)d_in[4];
    const float* nrm2 = (const float*)d_in[5];
    const float* res1 = (const float*)d_in[6];
    const float* res2 = (const float*)d_in[7];
    const float* R12  = (const float*)d_in[8];
    const float* t12  = (const float*)d_in[9];
    const float* R21  = (const float*)d_in[10];
    const float* t21  = (const float*)d_in[11];
    const int* npts1  = (const int*)d_in[12];
    const int* npts2  = (const int*)d_in[13];

    const int B = in_sizes[12];
    const int P = in_sizes[0] / (3 * B);
    const int chunks = (P + THREADS - 1) / THREADS;
    const size_t smem_scan = (size_t)3 * TILE_H * sizeof(float)
                           + (size_t)THREADS * CAP * sizeof(unsigned);   // 48KB + 56KB

    cudaFuncSetAttribute(knn_scan, cudaFuncAttributeMaxDynamicSharedMemorySize, (int)smem_scan);

    dim3 sgrid(chunks, B, 4);    // z = side*2 + half
    knn_scan<<<sgrid, THREADS, smem_scan>>>(xyz1, xyz2, R12, t12, R21, t21,
                                            npts1, npts2, B, P);
    dim3 mgrid(chunks, B, 2);
    knn_merge<<<mgrid, THREADS>>>(xyz1, xyz2, hsv1, hsv2, nrm1, nrm2,
                                  res1, res2, R12, t12, R21, t21,
                                  npts1, npts2, B, P);
    finalize_kernel<<<1, 256>>>(npts1, npts2, (float*)d_out, B, B * chunks, out_size);
}

// round 17
// speedup vs baseline: 1.3148x; 1.1914x over previous
#include <cuda_runtime.h>
#include <math.h>

#define KNN 20
#define THREADS 256
#define NSPLIT 3
#define TS 2752              // third-db per block (SoA: 3 * 11008B = 33KB)
#define CAP 40               // per-thread candidate buffer entries (40KB)
#define STEP 16              // candidates per drain-check
#define IDXMASK 0x1FFFu      // 13 bits: global db idx < 8192
#define KEYMASK 0xFFFFE000u
#define MAXP 8192

__device__ float g_partials[1024];
// top-20 key lists: [sb*NSPLIT+split][k][q]  (sb = side*B+b; q stride 1 -> coalesced)
__device__ unsigned g_knn[4 * NSPLIT * KNN * MAXP];

__device__ __forceinline__ unsigned long long addx2(unsigned long long a, unsigned long long b) {
    unsigned long long r;
    asm("add.rn.f32x2 %0, %1, %2;" : "=l"(r) : "l"(a), "l"(b));
    return r;
}
__device__ __forceinline__ unsigned long long mulx2(unsigned long long a, unsigned long long b) {
    unsigned long long r;
    asm("mul.rn.f32x2 %0, %1, %2;" : "=l"(r) : "l"(a), "l"(b));
    return r;
}
__device__ __forceinline__ unsigned long long fmax2(unsigned long long a, unsigned long long b, unsigned long long c) {
    unsigned long long r;
    asm("fma.rn.f32x2 %0, %1, %2, %3;" : "=l"(r) : "l"(a), "l"(b), "l"(c));
    return r;
}
__device__ __forceinline__ unsigned long long bcast2(float x) {
    unsigned long long r;
    asm("mov.b64 %0, {%1, %1};" : "=l"(r) : "r"(__float_as_uint(x)));
    return r;
}

__device__ __forceinline__ void bubble20(unsigned (&kd)[KNN], unsigned v) {
#pragma unroll
    for (int s = 0; s < KNN; ++s) {
        unsigned lo = min(kd[s], v);
        v = max(kd[s], v);
        kd[s] = lo;
    }
}

// ---------------- pass 1: third-db scan, emit per-query top-20 keys ----------------
__global__ void __launch_bounds__(THREADS, 3) knn_scan(
    const float* __restrict__ xyz1, const float* __restrict__ xyz2,
    const float* __restrict__ R12,  const float* __restrict__ t12,
    const float* __restrict__ R21,  const float* __restrict__ t21,
    const int* __restrict__ npts1,  const int* __restrict__ npts2,
    int B, int P)
{
    extern __shared__ float smemf[];
    float*    xs  = smemf;                     // [TS] negated transformed x
    float*    ys  = smemf + TS;
    float*    zs  = smemf + 2 * TS;
    unsigned* buf = (unsigned*)(smemf + 3 * TS);   // THREADS*CAP u32 = 40KB

    const int side  = blockIdx.z / NSPLIT;
    const int split = blockIdx.z % NSPLIT;
    const int b     = blockIdx.y;
    const int chunk = blockIdx.x;
    const int tid   = threadIdx.x;

    const float *q_xyz, *d_xyzp, *R, *T;
    int nq, ndb;
    const size_t o3 = (size_t)b * P * 3;
    if (side == 0) {
        q_xyz = xyz1 + o3; d_xyzp = xyz2 + o3;
        R = R12 + b * 9; T = t12 + b * 3;
        nq = npts1[b]; ndb = npts2[b];
    } else {
        q_xyz = xyz2 + o3; d_xyzp = xyz1 + o3;
        R = R21 + b * 9; T = t21 + b * 3;
        nq = npts2[b]; ndb = npts1[b];
    }

    const float r00 = R[0], r01 = R[1], r02 = R[2];
    const float r10 = R[3], r11 = R[4], r12_ = R[5];
    const float r20 = R[6], r21_ = R[7], r22 = R[8];
    const float t0 = T[0], t1 = T[1], t2 = T[2];

    const int dbBase = split * TS;
    int cnt = ndb - dbBase;
    if (cnt < 0) cnt = 0;
    if (cnt > TS) cnt = TS;
    const int cntp = (cnt + STEP - 1) & ~(STEP - 1);

    const int q = chunk * THREADS + tid;
    const bool active = (q < nq) && (cnt > 0);

    // ---- stage tile: transform while loading, store NEGATED, SoA ----
    for (int j = tid; j < cntp; j += THREADS) {
        float sx, sy, sz;
        if (j < cnt) {
            const int gj = dbBase + j;
            const float x = d_xyzp[3 * gj];
            const float y = d_xyzp[3 * gj + 1];
            const float z = d_xyzp[3 * gj + 2];
            sx = -fmaf(r00, x, fmaf(r01, y, fmaf(r02, z, t0)));
            sy = -fmaf(r10, x, fmaf(r11, y, fmaf(r12_, z, t1)));
            sz = -fmaf(r20, x, fmaf(r21_, y, fmaf(r22, z, t2)));
        } else {
            sx = sy = sz = -1.0e15f;           // sentinel: enormous distance
        }
        xs[j] = sx; ys[j] = sy; zs[j] = sz;
    }
    __syncthreads();

    float qx = 0.f, qy = 0.f, qz = 0.f;
    if (q < nq) {
        qx = q_xyz[3 * q]; qy = q_xyz[3 * q + 1]; qz = q_xyz[3 * q + 2];
    }
    const unsigned long long qx2 = bcast2(qx);
    const unsigned long long qy2 = bcast2(qy);
    const unsigned long long qz2 = bcast2(qz);

    unsigned kd[KNN];
#pragma unroll
    for (int s = 0; s < KNN; ++s) kd[s] = 0xFFFFFFFFu;

    unsigned thr = active ? 0xFFFFFFFFu : 0u;

    // u32 shared-window addressing for the candidate buffer (stride 1024B: conflict-free)
    const unsigned abase  = (unsigned)__cvta_generic_to_shared(buf + tid);
    unsigned       addr   = abase;
    const unsigned alimit = abase + (CAP - STEP) * THREADS * 4u;

    // ---- scan: packed-f32x2 phase A (LDS.128 batched), predicated-asm phase B ----
    for (int j0 = 0; j0 < cntp; j0 += STEP) {
        if (__any_sync(0xFFFFFFFFu, addr >= alimit)) {
            for (unsigned o = abase; o < addr; o += THREADS * 4u) {
                unsigned v;
                asm volatile("ld.shared.u32 %0, [%1];" : "=r"(v) : "r"(o));
                if (v < kd[KNN - 1]) bubble20(kd, v);
            }
            addr = abase;
            thr = active ? kd[KNN - 1] : 0u;
        }
        unsigned keys[STEP];
#pragma unroll
        for (int g = 0; g < STEP / 4; ++g) {
            const int j4 = j0 + g * 4;
            const unsigned gidx = (unsigned)(dbBase + j4);
            // LDS.128: register pairs are ready-made f32x2 operands
            const ulonglong2 xv = *reinterpret_cast<const ulonglong2*>(xs + j4);
            const ulonglong2 yv = *reinterpret_cast<const ulonglong2*>(ys + j4);
            const ulonglong2 zv = *reinterpret_cast<const ulonglong2*>(zs + j4);
            {
                const unsigned long long dx = addx2(qx2, xv.x);
                const unsigned long long dy = addx2(qy2, yv.x);
                const unsigned long long dz = addx2(qz2, zv.x);
                const unsigned long long d2 = fmax2(dx, dx, fmax2(dy, dy, mulx2(dz, dz)));
                keys[g * 4 + 0] = ((unsigned)d2 & KEYMASK) | (gidx + 0u);
                keys[g * 4 + 1] = ((unsigned)(d2 >> 32) & KEYMASK) | (gidx + 1u);
            }
            {
                const unsigned long long dx = addx2(qx2, xv.y);
                const unsigned long long dy = addx2(qy2, yv.y);
                const unsigned long long dz = addx2(qz2, zv.y);
                const unsigned long long d2 = fmax2(dx, dx, fmax2(dy, dy, mulx2(dz, dz)));
                keys[g * 4 + 2] = ((unsigned)d2 & KEYMASK) | (gidx + 2u);
                keys[g * 4 + 3] = ((unsigned)(d2 >> 32) & KEYMASK) | (gidx + 3u);
            }
        }
        // Phase B: predicated push, 3 issues/candidate (setp; @p st.shared; @p add)
#pragma unroll
        for (int u = 0; u < STEP; ++u) {
            asm volatile(
                "{\n\t"
                ".reg .pred p;\n\t"
                "setp.lt.u32 p, %1, %2;\n\t"
                "@p st.shared.u32 [%0], %1;\n\t"
                "@p add.u32 %0, %0, 1024;\n\t"
                "}"
                : "+r"(addr) : "r"(keys[u]), "r"(thr));
        }
    }
    // final drain
    for (unsigned o = abase; o < addr; o += THREADS * 4u) {
        unsigned v;
        asm volatile("ld.shared.u32 %0, [%1];" : "=r"(v) : "r"(o));
        if (v < kd[KNN - 1]) bubble20(kd, v);
    }

    // ---- write sorted key list (coalesced: q is the fastest dim) ----
    if (q < P) {
        const int sb = side * B + b;
        unsigned* dst = g_knn + ((size_t)(sb * NSPLIT + split) * KNN) * P + q;
#pragma unroll
        for (int k = 0; k < KNN; ++k) dst[(size_t)k * P] = kd[k];
    }
}

// ---------------- pass 2: merge splits + epilogue + block partials ----------------
__global__ void __launch_bounds__(THREADS) knn_merge(
    const float* __restrict__ xyz1, const float* __restrict__ xyz2,
    const float* __restrict__ hsv1, const float* __restrict__ hsv2,
    const float* __restrict__ nrm1, const float* __restrict__ nrm2,
    const float* __restrict__ res1, const float* __restrict__ res2,
    const float* __restrict__ R12,  const float* __restrict__ t12,
    const float* __restrict__ R21,  const float* __restrict__ t21,
    const int* __restrict__ npts1,  const int* __restrict__ npts2,
    int B, int P)
{
    const int side  = blockIdx.z;
    const int b     = blockIdx.y;
    const int chunk = blockIdx.x;
    const int tid   = threadIdx.x;

    const float *q_xyz, *q_hsv, *q_nrm, *q_res;
    const float *d_xyzp, *d_hsv, *d_nrm, *d_res;
    const float *R, *T;
    int nq;
    const size_t o3 = (size_t)b * P * 3;
    const size_t o1 = (size_t)b * P;
    if (side == 0) {
        q_xyz = xyz1 + o3; q_hsv = hsv1 + o3; q_nrm = nrm1 + o3; q_res = res1 + o1;
        d_xyzp = xyz2 + o3; d_hsv = hsv2 + o3; d_nrm = nrm2 + o3; d_res = res2 + o1;
        R = R12 + b * 9; T = t12 + b * 3;
        nq = npts1[b];
    } else {
        q_xyz = xyz2 + o3; q_hsv = hsv2 + o3; q_nrm = nrm2 + o3; q_res = res2 + o1;
        d_xyzp = xyz1 + o3; d_hsv = hsv1 + o3; d_nrm = nrm1 + o3; d_res = res1 + o1;
        R = R21 + b * 9; T = t21 + b * 3;
        nq = npts2[b];
    }

    const float r00 = R[0], r01 = R[1], r02 = R[2];
    const float r10 = R[3], r11 = R[4], r12_ = R[5];
    const float r20 = R[6], r21_ = R[7], r22 = R[8];
    const float t0 = T[0], t1 = T[1], t2 = T[2];

    const int q = chunk * THREADS + tid;
    const bool active = (q < nq);

    float acc = 0.0f;
    if (active) {
        const int sb = side * B + b;
        unsigned kd[KNN];
#pragma unroll
        for (int s = 0; s < KNN; ++s) kd[s] = 0xFFFFFFFFu;
        const unsigned* src = g_knn + ((size_t)(sb * NSPLIT) * KNN) * P + q;
#pragma unroll
        for (int k = 0; k < NSPLIT * KNN; ++k) {
            const unsigned v = src[(size_t)k * P];
            if (v < kd[KNN - 1]) bubble20(kd, v);
        }

        const float qx = q_xyz[3 * q], qy = q_xyz[3 * q + 1], qz = q_xyz[3 * q + 2];
        const float ell = fmaxf(0.15f * (qz - 10.0f) * 0.1f, 0.15f);
        const float inv_ls = 1.0f / (ell * ell);
        const float hq0 = q_hsv[3 * q], hq1 = q_hsv[3 * q + 1], hq2 = q_hsv[3 * q + 2];
        const float n0 = q_nrm[3 * q], n1 = q_nrm[3 * q + 1], n2 = q_nrm[3 * q + 2];
        const float rq = q_res[q];
        // R^T * n_q so dot with RAW db normal equals n_q . (R n_db)
        const float tn0 = r00 * n0 + r10 * n1 + r20 * n2;
        const float tn1 = r01 * n0 + r11 * n1 + r21_ * n2;
        const float tn2 = r02 * n0 + r12_ * n1 + r22 * n2;
#pragma unroll
        for (int k = 0; k < KNN; ++k) {
            const int j = (int)(kd[k] & IDXMASK);
            const float x = d_xyzp[3 * j];
            const float y = d_xyzp[3 * j + 1];
            const float z = d_xyzp[3 * j + 2];
            // same fmaf tree as scan; qx - px == qx + (-px) bit-exact
            const float px = fmaf(r00, x, fmaf(r01, y, fmaf(r02, z, t0)));
            const float py = fmaf(r10, x, fmaf(r11, y, fmaf(r12_, z, t1)));
            const float pz = fmaf(r20, x, fmaf(r21_, y, fmaf(r22, z, t2)));
            const float dx = qx - px, dy = qy - py, dz = qz - pz;
            const float d2 = fmaf(dx, dx, fmaf(dy, dy, dz * dz));   // exact
            const float wd = expf(-d2 * inv_ls);
            const float h0 = d_hsv[3 * j]     - hq0;
            const float h1 = d_hsv[3 * j + 1] - hq1;
            const float h2 = d_hsv[3 * j + 2] - hq2;
            const float cd = sqrtf(fmaf(h0, h0, fmaf(h1, h1, h2 * h2)) + 1e-12f);
            const float wc = expf(-cd * 5.0f);
            const float rk = d_res[j];
            const float alpha = 0.2f / (0.1f + rq + rk);
            const float dn = tn0 * d_nrm[3 * j] + tn1 * d_nrm[3 * j + 1] + tn2 * d_nrm[3 * j + 2];
            const float wn = fmaxf(dn * alpha, 0.0f);
            acc += wd * wc * wn;
        }
    }

    __shared__ float red[THREADS];
    red[tid] = acc;
    __syncthreads();
#pragma unroll
    for (int s = THREADS / 2; s > 0; s >>= 1) {
        if (tid < s) red[tid] += red[tid + s];
        __syncthreads();
    }
    if (tid == 0) {
        const int bid = (side * gridDim.y + b) * gridDim.x + chunk;
        g_partials[bid] = red[0];
    }
}

__global__ void finalize_kernel(const int* __restrict__ npts1,
                                const int* __restrict__ npts2,
                                float* __restrict__ out,
                                int B, int nblk_side, int out_size)
{
    __shared__ double sh0[256], sh1[256];
    const int tid = threadIdx.x;
    double a0 = 0.0, a1 = 0.0;
    for (int i = tid; i < nblk_side; i += 256) {
        a0 += (double)g_partials[i];
        a1 += (double)g_partials[nblk_side + i];
    }
    sh0[tid] = a0; sh1[tid] = a1;
    __syncthreads();
#pragma unroll
    for (int s = 128; s > 0; s >>= 1) {
        if (tid < s) { sh0[tid] += sh0[tid + s]; sh1[tid] += sh1[tid + s]; }
        __syncthreads();
    }
    if (tid == 0) {
        double c1 = 0.0, c2 = 0.0;
        for (int i = 0; i < B; ++i) { c1 += npts1[i]; c2 += npts2[i]; }
        const double k1 = sh0[0] / (c1 * (double)KNN);
        const double k2 = sh1[0] / (c2 * (double)KNN);
        out[0] = (float)(0.5 * (k1 + k2));
        for (int i = 1; i < out_size; ++i) out[i] = 0.0f;
    }
}

extern "C" void kernel_launch(void* const* d_in, const int* in_sizes, int n_in,
                              void* d_out, int out_size)
{
    const float* xyz1 = (const float*)d_in[0];
    const float* xyz2 = (const float*)d_in[1];
    const float* hsv1 = (const float*)d_in[2];
    const float* hsv2 = (const float*)d_in[3];
    const float* nrm1 = (const float*)d_in[4];
    const float* nrm2 = (const float*)d_in[5];
    const float* res1 = (const float*)d_in[6];
    const float* res2 = (const float*)d_in[7];
    const float* R12  = (const float*)d_in[8];
    const float* t12  = (const float*)d_in[9];
    const float* R21  = (const float*)d_in[10];
    const float* t21  = (const float*)d_in[11];
    const int* npts1  = (const int*)d_in[12];
    const int* npts2  = (const int*)d_in[13];

    const int B = in_sizes[12];
    const int P = in_sizes[0] / (3 * B);
    const int chunks = (P + THREADS - 1) / THREADS;
    const size_t smem_scan = (size_t)3 * TS * sizeof(float)
                           + (size_t)THREADS * CAP * sizeof(unsigned);   // 33KB + 40KB

    cudaFuncSetAttribute(knn_scan, cudaFuncAttributeMaxDynamicSharedMemorySize, (int)smem_scan);

    dim3 sgrid(chunks, B, 2 * NSPLIT);    // z = side*NSPLIT + split
    knn_scan<<<sgrid, THREADS, smem_scan>>>(xyz1, xyz2, R12, t12, R21, t21,
                                            npts1, npts2, B, P);
    dim3 mgrid(chunks, B, 2);
    knn_merge<<<mgrid, THREADS>>>(xyz1, xyz2, hsv1, hsv2, nrm1, nrm2,
                                  res1, res2, R12, t12, R21, t21,
                                  npts1, npts2, B, P);
    finalize_kernel<<<1, 256>>>(npts1, npts2, (float*)d_out, B, B * chunks, out_size);
}